// round 7
// baseline (speedup 1.0000x reference)
#include <cuda_runtime.h>

#define NSC       4096
#define NT        14
#define THREADS   512

// shared layout: [0,1024) Tb[m]=e^{2pi i m/2048}; [1024,3072) Y0; [3072,5120) Y1
__global__ __launch_bounds__(THREADS) void tdi_kernel(const float* __restrict__ pr,
                                                      const float* __restrict__ pi,
                                                      float2* __restrict__ out,   // REAL PARTS ONLY, [b][t][sc]
                                                      long long n0,       // elems in pr
                                                      long long n1,       // elems in pi
                                                      long long cap_f2)   // float2 capacity of out
{
    __shared__ float2 sh[5120];   // 40 KB
    float2* Tb = sh;
    float2* Y0 = sh + 1024;
    float2* Y1 = sh + 3072;

    const int tid = threadIdx.x;
    const int b   = blockIdx.x;
    const long long base = (long long)b * 4096;

    // Twiddle table Tb[m] = e^{+2*pi*i*m/2048}, m in [0,1024)
    for (int m = tid; m < 1024; m += THREADS) {
        float ang = (float)m * 3.0679615757712823e-3f;   // pi/1024
        float s, c;
        sincosf(ang, &s, &c);
        Tb[m] = make_float2(c, s);
    }

    // Load both pilot symbols (complex), each pointer guarded by ITS OWN size.
    for (int n = tid; n < 2048; n += THREADS) {
        long long i0 = base + n;
        long long i1 = base + n + 2048;
        float r0 = (i0 < n0) ? pr[i0] : 0.0f;
        float m0 = (i0 < n1) ? pi[i0] : 0.0f;
        float r1 = (i1 < n0) ? pr[i1] : 0.0f;
        float m1 = (i1 < n1) ? pi[i1] : 0.0f;
        Y0[n] = make_float2(r0, m0);
        Y1[n] = make_float2(r1, m1);
    }
    __syncthreads();

    // Per symbol: forward DIF FFT (natural->bitrev), pointwise twiddle in
    // bitrev domain, inverse DIT FFT (bitrev->natural) => odd-subcarrier
    // interpolants. Even subcarriers equal the input pilots exactly.
    for (int s = 0; s < 2; s++) {
        float2* A = s ? Y1 : Y0;

        // forward DIF, twiddle conj(Tb[j*1024/h])
        for (int h = 1024; h >= 1; h >>= 1) {
            const int stride2 = 1024 / h;
            for (int q = tid; q < 1024; q += THREADS) {
                int j  = q & (h - 1);
                int i0 = ((q - j) << 1) + j;
                int i1 = i0 + h;
                float2 u = A[i0], v = A[i1];
                float2 d  = make_float2(u.x - v.x, u.y - v.y);
                float2 tw = Tb[j * stride2];
                A[i0] = make_float2(u.x + v.x, u.y + v.y);
                A[i1] = make_float2(d.x * tw.x + d.y * tw.y,
                                    d.y * tw.x - d.x * tw.y);
            }
            __syncthreads();
        }

        // pointwise: position p holds X[rev(p)]; multiply by w[rev(p)]/2048
        for (int p = tid; p < 2048; p += THREADS) {
            int k = (int)(__brev((unsigned)p) >> 21);   // 11-bit bit-reverse
            float ang = (float)k * 1.5339807878856412e-3f;   // pi/2048
            float ws, wc;
            sincosf(ang, &ws, &wc);
            float sgn = (k < 1024) ? (1.0f / 2048.0f) : (-1.0f / 2048.0f);
            float2 a = A[p];
            A[p] = make_float2(sgn * (a.x * wc - a.y * ws),
                               sgn * (a.x * ws + a.y * wc));
        }
        __syncthreads();

        // inverse DIT, twiddle Tb[j*1024/h]
        for (int h = 1; h <= 1024; h <<= 1) {
            const int stride2 = 1024 / h;
            for (int q = tid; q < 1024; q += THREADS) {
                int j  = q & (h - 1);
                int i0 = ((q - j) << 1) + j;
                int i1 = i0 + h;
                float2 u  = A[i0], v = A[i1];
                float2 tw = Tb[j * stride2];
                float2 vt = make_float2(v.x * tw.x - v.y * tw.y,
                                        v.x * tw.y + v.y * tw.x);
                A[i0] = make_float2(u.x + vt.x, u.y + vt.y);
                A[i1] = make_float2(u.x - vt.x, u.y - vt.y);
            }
            __syncthreads();
        }
    }

    // output: real parts only, float layout [b][t][sc].
    // One float2 store covers subcarriers {2r, 2r+1}:
    //   float index q = b*57344 + t*4096 + 2r  ->  float2 index q/2.
    const long long obf2 = (long long)b * (NT * NSC / 2);
    for (int r = tid; r < 2048; r += THREADS) {
        long long i0 = base + r;
        long long i1 = base + r + 2048;
        float er0 = (i0 < n0) ? pr[i0] : 0.0f;   // re even, symbol 0
        float er1 = (i1 < n0) ? pr[i1] : 0.0f;   // re even, symbol 1
        float or0 = Y0[r].x;                      // re odd,  symbol 0
        float or1 = Y1[r].x;                      // re odd,  symbol 1
        #pragma unroll
        for (int t = 0; t < NT; t++) {
            float w = fminf(fmaxf((float)(t - 2) * (1.0f / 9.0f), 0.0f), 1.0f);
            long long f2 = obf2 + (long long)t * (NSC / 2) + r;
            if (f2 < cap_f2) {
                out[f2] = make_float2(er0 + (er1 - er0) * w,
                                      or0 + (or1 - or0) * w);
            }
        }
    }
}

extern "C" void kernel_launch(void* const* d_in, const int* in_sizes, int n_in,
                              void* d_out, int out_size) {
    const float* pr = (const float*)d_in[0];
    const int ilast = (n_in > 1) ? (n_in - 1) : 0;
    const float* pi = (const float*)d_in[ilast];

    const long long n0 = (long long)in_sizes[0];
    const long long n1 = (long long)in_sizes[ilast];

    // Batch count from input (4096 pilot floats per batch), clamped by what
    // the output can hold (57344 floats per batch).
    long long B = n0 / 4096;
    long long B_cap = (long long)out_size / ((long long)NT * NSC);
    if (B_cap < B) B = B_cap;
    if (B < 1) B = 1;
    if (B > 65535) B = 65535;

    const long long cap_f2 = (long long)out_size / 2;   // float2 capacity of out

    tdi_kernel<<<(int)B, THREADS>>>(pr, pi, (float2*)d_out, n0, n1, cap_f2);
}

// round 8
// speedup vs baseline: 1.5714x; 1.5714x over previous
#include <cuda_runtime.h>

#define NSC       4096
#define NT        14
#define THREADS   512
#define PAD(f)    ((f) + ((f) >> 3))

__device__ __forceinline__ float2 cadd(float2 a, float2 b) { return make_float2(a.x + b.x, a.y + b.y); }
__device__ __forceinline__ float2 csub(float2 a, float2 b) { return make_float2(a.x - b.x, a.y - b.y); }
__device__ __forceinline__ float2 cmul(float2 a, float2 b) {       // a*b
    return make_float2(a.x * b.x - a.y * b.y, a.x * b.y + a.y * b.x);
}
__device__ __forceinline__ float2 cmulc(float2 a, float2 b) {      // a*conj(b)
    return make_float2(a.x * b.x + a.y * b.y, a.y * b.x - a.x * b.y);
}

// Forward radix-4 DIF stage, L=4h. Twiddles conj(Tb[j*str]), str=512/h.
__device__ __forceinline__ void fwd4(float2* __restrict__ A, const float2* __restrict__ Tb,
                                     int q, int h, int str) {
    int j    = q & (h - 1);
    int base = ((q - j) << 2) + j;
    float2 t0 = A[PAD(base)];
    float2 t1 = A[PAD(base + h)];
    float2 t2 = A[PAD(base + 2 * h)];
    float2 t3 = A[PAD(base + 3 * h)];
    float2 a = cadd(t0, t2), b = csub(t0, t2);
    float2 c = cadd(t1, t3), d = csub(t1, t3);
    float2 B0 = cadd(a, c);
    float2 B2 = csub(a, c);
    float2 B1 = make_float2(b.x + d.y, b.y - d.x);   // b - i d
    float2 B3 = make_float2(b.x - d.y, b.y + d.x);   // b + i d
    float2 e1 = Tb[j * str];
    float2 e2 = Tb[2 * j * str];
    A[PAD(base)]         = B0;
    A[PAD(base + h)]     = cmulc(B1, e1);
    A[PAD(base + 2 * h)] = cmulc(B2, e2);
    A[PAD(base + 3 * h)] = cmulc(cmulc(B3, e1), e2);
}

// Inverse radix-4 DIT stage (transpose of fwd4, twiddles Tb[j*str]).
__device__ __forceinline__ void inv4(float2* __restrict__ A, const float2* __restrict__ Tb,
                                     int q, int h, int str) {
    int j    = q & (h - 1);
    int base = ((q - j) << 2) + j;
    float2 Z0 = A[PAD(base)];
    float2 Z1 = A[PAD(base + h)];
    float2 Z2 = A[PAD(base + 2 * h)];
    float2 Z3 = A[PAD(base + 3 * h)];
    float2 e1 = Tb[j * str];
    float2 e2 = Tb[2 * j * str];
    float2 w1 = cmul(Z1, e1);
    float2 w2 = cmul(Z2, e2);
    float2 w3 = cmul(cmul(Z3, e1), e2);
    float2 a = cadd(Z0, w2), b = csub(Z0, w2);
    float2 c = cadd(w1, w3), d = csub(w1, w3);
    A[PAD(base)]         = cadd(a, c);
    A[PAD(base + 2 * h)] = csub(a, c);
    A[PAD(base + h)]     = make_float2(b.x - d.y, b.y + d.x);   // b + i d
    A[PAD(base + 3 * h)] = make_float2(b.x + d.y, b.y - d.x);   // b - i d
}

// shared: Tb[1024] | Y0[2304 padded] | Y1[2304 padded]  = 5632 float2 = 44 KB
__global__ __launch_bounds__(THREADS) void tdi_kernel(const float* __restrict__ pr,
                                                      const float* __restrict__ pi,
                                                      float2* __restrict__ out,   // real parts, [b][t][sc]
                                                      long long n0, long long n1,
                                                      long long cap_f2)
{
    __shared__ float2 sh[5632];
    float2* Tb = sh;
    float2* Y0 = sh + 1024;
    float2* Y1 = sh + 1024 + 2304;

    const int tid = threadIdx.x;
    const int b   = blockIdx.x;
    const long long base = (long long)b * 4096;

    // Tb[m] = e^{+2*pi*i*m/2048}
    for (int m = tid; m < 1024; m += THREADS) {
        float s, c;
        sincosf((float)m * 3.0679615757712823e-3f, &s, &c);   // pi/1024
        Tb[m] = make_float2(c, s);
    }
    for (int n = tid; n < 2048; n += THREADS) {
        long long i0 = base + n;
        long long i1 = base + n + 2048;
        float r0 = (i0 < n0) ? pr[i0] : 0.0f;
        float m0 = (i0 < n1) ? pi[i0] : 0.0f;
        float r1 = (i1 < n0) ? pr[i1] : 0.0f;
        float m1 = (i1 < n1) ? pi[i1] : 0.0f;
        Y0[PAD(n)] = make_float2(r0, m0);
        Y1[PAD(n)] = make_float2(r1, m1);
    }
    __syncthreads();

    // ---- forward radix-4 DIF: L = 2048,512,128,32,8  (h = 512,128,32,8,2)
    for (int h = 512; h >= 2; h >>= 2) {
        int str = 512 / h;
        fwd4(Y0, Tb, tid, h, str);
        fwd4(Y1, Tb, tid, h, str);
        __syncthreads();
    }

    // ---- fused: forward radix-2 (L=2) + pointwise w[k]/2048 + inverse radix-2
    // pair (p, p+1), p = 2m; k0 = base-4-digit-reverse of p (bit10 = 0);
    // w[k0+1024] = -i * w[k0].
    for (int m = tid; m < 1024; m += THREADS) {
        int p  = 2 * m;
        int k0 = ((p >> 9) & 3) | (((p >> 7) & 3) << 2) | (((p >> 5) & 3) << 4)
               | (((p >> 3) & 3) << 6) | (((p >> 1) & 3) << 8);
        float sn, cs;
        sincosf((float)k0 * 1.5339807878856412e-3f, &sn, &cs);   // 2*pi/4096
        float2 w0  = make_float2(cs * (1.0f / 2048.0f), sn * (1.0f / 2048.0f));
        float2 w0n = make_float2(w0.y, -w0.x);                    // -i * w0
        {
            float2 t0 = Y0[PAD(p)], t1 = Y0[PAD(p + 1)];
            float2 s = cmul(cadd(t0, t1), w0);
            float2 d = cmul(csub(t0, t1), w0n);
            Y0[PAD(p)]     = cadd(s, d);
            Y0[PAD(p + 1)] = csub(s, d);
        }
        {
            float2 t0 = Y1[PAD(p)], t1 = Y1[PAD(p + 1)];
            float2 s = cmul(cadd(t0, t1), w0);
            float2 d = cmul(csub(t0, t1), w0n);
            Y1[PAD(p)]     = cadd(s, d);
            Y1[PAD(p + 1)] = csub(s, d);
        }
    }
    __syncthreads();

    // ---- inverse radix-4 DIT: L = 8,32,128,512,2048  (h = 2,8,32,128,512)
    for (int h = 2; h <= 512; h <<= 2) {
        int str = 512 / h;
        inv4(Y0, Tb, tid, h, str);
        inv4(Y1, Tb, tid, h, str);
        __syncthreads();
    }

    // ---- output: real parts only, [b][t][sc]; float2 covers sc {2r, 2r+1}
    const long long obf2 = (long long)b * (NT * NSC / 2);
    for (int r = tid; r < 2048; r += THREADS) {
        long long i0 = base + r;
        long long i1 = base + r + 2048;
        float er0 = (i0 < n0) ? pr[i0] : 0.0f;
        float er1 = (i1 < n0) ? pr[i1] : 0.0f;
        float or0 = Y0[PAD(r)].x;
        float or1 = Y1[PAD(r)].x;
        #pragma unroll
        for (int t = 0; t < NT; t++) {
            float w = fminf(fmaxf((float)(t - 2) * (1.0f / 9.0f), 0.0f), 1.0f);
            long long f2 = obf2 + (long long)t * (NSC / 2) + r;
            if (f2 < cap_f2) {
                out[f2] = make_float2(er0 + (er1 - er0) * w,
                                      or0 + (or1 - or0) * w);
            }
        }
    }
}

extern "C" void kernel_launch(void* const* d_in, const int* in_sizes, int n_in,
                              void* d_out, int out_size) {
    const float* pr = (const float*)d_in[0];
    const int ilast = (n_in > 1) ? (n_in - 1) : 0;
    const float* pi = (const float*)d_in[ilast];

    const long long n0 = (long long)in_sizes[0];
    const long long n1 = (long long)in_sizes[ilast];

    long long B = n0 / 4096;
    long long B_cap = (long long)out_size / ((long long)NT * NSC);
    if (B_cap < B) B = B_cap;
    if (B < 1) B = 1;
    if (B > 65535) B = 65535;

    const long long cap_f2 = (long long)out_size / 2;

    tdi_kernel<<<(int)B, THREADS>>>(pr, pi, (float2*)d_out, n0, n1, cap_f2);
}

// round 9
// speedup vs baseline: 2.3710x; 1.5089x over previous
#include <cuda_runtime.h>

#define NSC       4096
#define NT        14
#define THREADS   512
#define PAD(f)    ((f) + ((f) >> 3))
#define RSQ2      0.70710678118654752f

__device__ __forceinline__ float2 cadd(float2 a, float2 b) { return make_float2(a.x + b.x, a.y + b.y); }
__device__ __forceinline__ float2 csub(float2 a, float2 b) { return make_float2(a.x - b.x, a.y - b.y); }
__device__ __forceinline__ float2 cmul(float2 a, float2 b) {
    return make_float2(a.x * b.x - a.y * b.y, a.x * b.y + a.y * b.x);
}

// Forward radix-8 DIF stage (L=8h). Output k twiddled by conj(Tb[j*str])^k.
__device__ __forceinline__ void fwd8(float2* __restrict__ A, const float2* __restrict__ Tb,
                                     int q, int h, int str) {
    int j    = q & (h - 1);
    int base = ((q - j) << 3) + j;
    float2 t0 = A[PAD(base)],         t1 = A[PAD(base + h)];
    float2 t2 = A[PAD(base + 2 * h)], t3 = A[PAD(base + 3 * h)];
    float2 t4 = A[PAD(base + 4 * h)], t5 = A[PAD(base + 5 * h)];
    float2 t6 = A[PAD(base + 6 * h)], t7 = A[PAD(base + 7 * h)];

    float2 a0 = cadd(t0, t4), a1 = cadd(t1, t5), a2 = cadd(t2, t6), a3 = cadd(t3, t7);
    float2 b0 = csub(t0, t4), b1 = csub(t1, t5), b2 = csub(t2, t6), b3 = csub(t3, t7);
    // even half: DFT4(a), forward (w = e^{-2pi i/4})
    float2 c0 = cadd(a0, a2), c1 = csub(a0, a2), c2 = cadd(a1, a3), c3 = csub(a1, a3);
    float2 X0 = cadd(c0, c2), X4 = csub(c0, c2);
    float2 X2 = make_float2(c1.x + c3.y, c1.y - c3.x);   // c1 - i c3
    float2 X6 = make_float2(c1.x - c3.y, c1.y + c3.x);   // c1 + i c3
    // odd half: twiddle b by w8^k then DFT4
    float2 d0 = b0;
    float2 d1 = make_float2(RSQ2 * (b1.x + b1.y), RSQ2 * (b1.y - b1.x));  // b1*e^{-i pi/4}
    float2 d2 = make_float2(b2.y, -b2.x);                                  // b2*(-i)
    float2 d3 = make_float2(RSQ2 * (b3.y - b3.x), RSQ2 * (-(b3.x + b3.y))); // b3*e^{-3i pi/4}
    float2 e0 = cadd(d0, d2), ee1 = csub(d0, d2), e2 = cadd(d1, d3), e3 = csub(d1, d3);
    float2 X1 = cadd(e0, e2), X5 = csub(e0, e2);
    float2 X3 = make_float2(ee1.x + e3.y, ee1.y - e3.x);
    float2 X7 = make_float2(ee1.x - e3.y, ee1.y + e3.x);

    // twiddle powers of wc = conj(Tb[j*str])
    float2 w1 = Tb[j * str]; w1.y = -w1.y;
    float2 w2 = cmul(w1, w1);
    float2 w3 = cmul(w2, w1);
    float2 w4 = cmul(w2, w2);
    float2 w5 = cmul(w4, w1);
    float2 w6 = cmul(w4, w2);
    float2 w7 = cmul(w4, w3);
    A[PAD(base)]         = X0;
    A[PAD(base + h)]     = cmul(X1, w1);
    A[PAD(base + 2 * h)] = cmul(X2, w2);
    A[PAD(base + 3 * h)] = cmul(X3, w3);
    A[PAD(base + 4 * h)] = cmul(X4, w4);
    A[PAD(base + 5 * h)] = cmul(X5, w5);
    A[PAD(base + 6 * h)] = cmul(X6, w6);
    A[PAD(base + 7 * h)] = cmul(X7, w7);
}

// Inverse radix-8 DIT stage: twiddle inputs by Tb[j*str]^k, then IDFT8.
__device__ __forceinline__ void inv8(float2* __restrict__ A, const float2* __restrict__ Tb,
                                     int q, int h, int str) {
    int j    = q & (h - 1);
    int base = ((q - j) << 3) + j;
    float2 w1 = Tb[j * str];
    float2 w2 = cmul(w1, w1);
    float2 w3 = cmul(w2, w1);
    float2 w4 = cmul(w2, w2);
    float2 w5 = cmul(w4, w1);
    float2 w6 = cmul(w4, w2);
    float2 w7 = cmul(w4, w3);
    float2 t0 = A[PAD(base)];
    float2 t1 = cmul(A[PAD(base + h)],     w1);
    float2 t2 = cmul(A[PAD(base + 2 * h)], w2);
    float2 t3 = cmul(A[PAD(base + 3 * h)], w3);
    float2 t4 = cmul(A[PAD(base + 4 * h)], w4);
    float2 t5 = cmul(A[PAD(base + 5 * h)], w5);
    float2 t6 = cmul(A[PAD(base + 6 * h)], w6);
    float2 t7 = cmul(A[PAD(base + 7 * h)], w7);

    float2 a0 = cadd(t0, t4), a1 = cadd(t1, t5), a2 = cadd(t2, t6), a3 = cadd(t3, t7);
    float2 b0 = csub(t0, t4), b1 = csub(t1, t5), b2 = csub(t2, t6), b3 = csub(t3, t7);
    // even half: IDFT4(a) (w = e^{+2pi i/4})
    float2 c0 = cadd(a0, a2), c1 = csub(a0, a2), c2 = cadd(a1, a3), c3 = csub(a1, a3);
    float2 X0 = cadd(c0, c2), X4 = csub(c0, c2);
    float2 X2 = make_float2(c1.x - c3.y, c1.y + c3.x);   // c1 + i c3
    float2 X6 = make_float2(c1.x + c3.y, c1.y - c3.x);   // c1 - i c3
    // odd half: twiddle b by w8^{+k} then IDFT4
    float2 d0 = b0;
    float2 d1 = make_float2(RSQ2 * (b1.x - b1.y), RSQ2 * (b1.y + b1.x));    // b1*e^{+i pi/4}
    float2 d2 = make_float2(-b2.y, b2.x);                                    // b2*(+i)
    float2 d3 = make_float2(RSQ2 * (-(b3.x + b3.y)), RSQ2 * (b3.x - b3.y)); // b3*e^{+3i pi/4}
    float2 e0 = cadd(d0, d2), ee1 = csub(d0, d2), e2 = cadd(d1, d3), e3 = csub(d1, d3);
    float2 X1 = cadd(e0, e2), X5 = csub(e0, e2);
    float2 X3 = make_float2(ee1.x - e3.y, ee1.y + e3.x);
    float2 X7 = make_float2(ee1.x + e3.y, ee1.y - e3.x);

    A[PAD(base)]         = X0;
    A[PAD(base + h)]     = X1;
    A[PAD(base + 2 * h)] = X2;
    A[PAD(base + 3 * h)] = X3;
    A[PAD(base + 4 * h)] = X4;
    A[PAD(base + 5 * h)] = X5;
    A[PAD(base + 6 * h)] = X6;
    A[PAD(base + 7 * h)] = X7;
}

// shared: Tb[1024] | Y0[2304 padded] | Y1[2304 padded] = 5632 float2 = 45 KB
__global__ __launch_bounds__(THREADS) void tdi_kernel(const float* __restrict__ pr,
                                                      const float* __restrict__ pi,
                                                      float2* __restrict__ out,   // real parts, [b][t][sc]
                                                      long long n0, long long n1,
                                                      long long cap_f2)
{
    __shared__ float2 sh[5632];
    float2* Tb = sh;
    float2* Y0 = sh + 1024;
    float2* Y1 = sh + 1024 + 2304;

    const int tid = threadIdx.x;
    const int b   = blockIdx.x;
    const long long base = (long long)b * 4096;

    for (int m = tid; m < 1024; m += THREADS) {
        float s, c;
        sincosf((float)m * 3.0679615757712823e-3f, &s, &c);   // 2*pi/2048
        Tb[m] = make_float2(c, s);
    }
    for (int n = tid; n < 2048; n += THREADS) {
        long long i0 = base + n;
        long long i1 = base + n + 2048;
        float r0 = (i0 < n0) ? pr[i0] : 0.0f;
        float m0 = (i0 < n1) ? pi[i0] : 0.0f;
        float r1 = (i1 < n0) ? pr[i1] : 0.0f;
        float m1 = (i1 < n1) ? pi[i1] : 0.0f;
        Y0[PAD(n)] = make_float2(r0, m0);
        Y1[PAD(n)] = make_float2(r1, m1);
    }
    __syncthreads();

    // thread -> (array, butterfly q): 256 butterflies per array per stage
    const int q   = tid & 255;
    float2* Aq    = (tid >> 8) ? Y1 : Y0;

    // forward radix-8 DIF: h = 256, 32, 4
    fwd8(Aq, Tb, q, 256, 1);  __syncthreads();
    fwd8(Aq, Tb, q, 32,  8);  __syncthreads();
    fwd8(Aq, Tb, q, 4,   64); __syncthreads();

    // fused middle: forward radix-4 (L=4) + pointwise w[k]/2048 + inverse radix-4
    {
        int m = tid;                               // quad index, one per thread per array
        int revm = ((m & 7) << 6) | (m & 56) | (m >> 6);   // octal-digit reverse
        float sn, cs;
        sincosf((float)revm * 1.5339807878856412e-3f, &sn, &cs);   // 2*pi/4096
        float2 w0 = make_float2(cs * (1.0f / 2048.0f), sn * (1.0f / 2048.0f));
        float2 wA = make_float2(RSQ2 * (w0.x - w0.y), RSQ2 * (w0.x + w0.y));  // w0*u
        float2 wB = make_float2(w0.y, -w0.x);                                  // -i*w0
        float2 wC = make_float2(RSQ2 * (w0.x + w0.y), RSQ2 * (w0.y - w0.x));  // w0*conj(u)
        int p = 4 * m;
        #pragma unroll
        for (int s = 0; s < 2; s++) {
            float2* A = s ? Y1 : Y0;
            float2 t0 = A[PAD(p)],     t1 = A[PAD(p + 1)];
            float2 t2 = A[PAD(p + 2)], t3 = A[PAD(p + 3)];
            float2 a = cadd(t0, t2), bb = csub(t0, t2);
            float2 c = cadd(t1, t3), d  = csub(t1, t3);
            float2 F0 = cadd(a, c);
            float2 F1 = make_float2(bb.x + d.y, bb.y - d.x);   // b - i d
            float2 F2 = csub(a, c);
            float2 F3 = make_float2(bb.x - d.y, bb.y + d.x);   // b + i d
            float2 G0 = cmul(F0, w0), G1 = cmul(F1, wA);
            float2 G2 = cmul(F2, wB), G3 = cmul(F3, wC);
            float2 ap = cadd(G0, G2), bp = csub(G0, G2);
            float2 cp = cadd(G1, G3), dp = csub(G1, G3);
            A[PAD(p)]     = cadd(ap, cp);
            A[PAD(p + 2)] = csub(ap, cp);
            A[PAD(p + 1)] = make_float2(bp.x - dp.y, bp.y + dp.x);  // b + i d
            A[PAD(p + 3)] = make_float2(bp.x + dp.y, bp.y - dp.x);  // b - i d
        }
    }
    __syncthreads();

    // inverse radix-8 DIT: h = 4, 32, 256
    inv8(Aq, Tb, q, 4,   64); __syncthreads();
    inv8(Aq, Tb, q, 32,  8);  __syncthreads();
    inv8(Aq, Tb, q, 256, 1);  __syncthreads();

    // output: real parts only, [b][t][sc]; float2 covers sc {2r, 2r+1}
    const long long obf2 = (long long)b * (NT * NSC / 2);
    for (int r = tid; r < 2048; r += THREADS) {
        long long i0 = base + r;
        long long i1 = base + r + 2048;
        float er0 = (i0 < n0) ? pr[i0] : 0.0f;
        float er1 = (i1 < n0) ? pr[i1] : 0.0f;
        float or0 = Y0[PAD(r)].x;
        float or1 = Y1[PAD(r)].x;
        #pragma unroll
        for (int t = 0; t < NT; t++) {
            float w = fminf(fmaxf((float)(t - 2) * (1.0f / 9.0f), 0.0f), 1.0f);
            long long f2 = obf2 + (long long)t * (NSC / 2) + r;
            if (f2 < cap_f2) {
                out[f2] = make_float2(er0 + (er1 - er0) * w,
                                      or0 + (or1 - or0) * w);
            }
        }
    }
}

extern "C" void kernel_launch(void* const* d_in, const int* in_sizes, int n_in,
                              void* d_out, int out_size) {
    const float* pr = (const float*)d_in[0];
    const int ilast = (n_in > 1) ? (n_in - 1) : 0;
    const float* pi = (const float*)d_in[ilast];

    const long long n0 = (long long)in_sizes[0];
    const long long n1 = (long long)in_sizes[ilast];

    long long B = n0 / 4096;
    long long B_cap = (long long)out_size / ((long long)NT * NSC);
    if (B_cap < B) B = B_cap;
    if (B < 1) B = 1;
    if (B > 65535) B = 65535;

    const long long cap_f2 = (long long)out_size / 2;

    tdi_kernel<<<(int)B, THREADS>>>(pr, pi, (float2*)d_out, n0, n1, cap_f2);
}